// round 14
// baseline (speedup 1.0000x reference)
#include <cuda_runtime.h>
#include <math.h>

#define EE 24000
#define NTOP 1500
#define NL (EE+NTOP)
typedef unsigned long long ull;

__device__ float g_buf[11600000];

#define O_AT   0
#define O_A2   2250000
#define O_P    4500000
#define O_SPT  6750000
#define O_U    8800000
#define O_X    10850000
#define O_XB   10946000
#define O_XQ   11042000
#define O_XC   11138000
#define O_SUM  11234000
#define O_ENC  11330000
#define O_ES   11426000
#define O_EB   11452000
#define O_MS   11478000
#define M_AGG 0
#define M_DEN 1500
#define M_CNTE 3000
#define M_AV 6000
#define M_BV 7500
#define M_C3 9000
#define M_FIT 10500
#define M_FITK 12000
#define M_PERM 13500
#define M_XS 15000

__device__ __forceinline__ unsigned fenc(float f){unsigned u=__float_as_uint(f);return (u&0x80000000u)?~u:(u|0x80000000u);}
__device__ __forceinline__ float fdec(unsigned v){return (v&0x80000000u)?__uint_as_float(v&0x7FFFFFFFu):__uint_as_float(~v);}
__device__ __forceinline__ void ledge(int e,const int*es,const int*ed,int&s,int&d){ if(e<EE){s=es[e];d=ed[e];}else{s=e-EE;d=s;} }

__device__ __forceinline__ ull pk2(float x,float y){
  ull r; asm("mov.b64 %0, {%1, %2};" : "=l"(r) : "r"(__float_as_uint(x)), "r"(__float_as_uint(y))); return r;
}
__device__ __forceinline__ ull fma2(ull a,ull b,ull c){
  ull d; asm("fma.rn.f32x2 %0, %1, %2, %3;" : "=l"(d) : "l"(a), "l"(b), "l"(c)); return d;
}
__device__ __forceinline__ float2 upk2(ull v){
  unsigned lo,hi; asm("mov.b64 {%0, %1}, %2;" : "=r"(lo), "=r"(hi) : "l"(v));
  return make_float2(__uint_as_float(lo),__uint_as_float(hi));
}

// C[M,N] = act((acc?C:0) + A[M,K]@B[K,N] + bias)   (feast only)
__global__ void k_ngemm(const float*__restrict__ A,const float*__restrict__ B,const float*__restrict__ bias,
                        float*__restrict__ C,int M,int N,int K,int acc,int act){
  int col=threadIdx.x, row=blockIdx.x*blockDim.y+threadIdx.y;
  if(row>=M)return;
  float s=0.f; const float*a=A+(size_t)row*K;
  for(int k=0;k<K;k++) s+=a[k]*B[(size_t)k*N+col];
  if(bias)s+=bias[col];
  if(acc)s+=C[(size_t)row*N+col];
  if(act==1)s=fmaxf(s,0.f); else if(act==2)s=(s>0.f)?s:expm1f(s);
  C[(size_t)row*N+col]=s;
}

// split-K partial GEMM, N=64, double-buffered
__global__ void __launch_bounds__(256) k_spk(const float*__restrict__ A,const float*__restrict__ X,
                                             float*__restrict__ part,int M,int K,int chunk){
  __shared__ float As[2][16][64], Bs[2][16][64];
  int s=blockIdx.y, m0=blockIdx.x*64;
  int k0=s*chunk, k1=min(K,k0+chunk);
  int tid=threadIdx.x, tx=tid&15, ty=tid>>4;
  ull acc2[4][2]={};
  int nt=(k1-k0+15)/16;
  if(nt<=0){
    #pragma unroll
    for(int i=0;i<4;i++){int gm=m0+ty*4+i; if(gm>=M)continue;
      float* pr=part+((size_t)s*M+gm)*64+tx*4;
      pr[0]=0;pr[1]=0;pr[2]=0;pr[3]=0;}
    return;
  }
  float ra[4], rb[4];
  #define SLD(k0v) { \
    _Pragma("unroll") \
    for(int j=0;j<4;j++){int idx=tid*4+j; int m=idx>>4,kk=idx&15; int gm=m0+m,gk=(k0v)+kk; \
      ra[j]=(gm<M&&gk<k1)?A[(size_t)gm*K+gk]:0.f;} \
    _Pragma("unroll") \
    for(int j=0;j<4;j++){int idx=tid*4+j; int kk=idx>>6,nn=idx&63; int gk=(k0v)+kk; \
      rb[j]=(gk<k1)?X[(size_t)gk*64+nn]:0.f;} }
  #define SST(buf) { \
    _Pragma("unroll") \
    for(int j=0;j<4;j++){int idx=tid*4+j; As[buf][idx&15][idx>>4]=ra[j];} \
    _Pragma("unroll") \
    for(int j=0;j<4;j++){int idx=tid*4+j; Bs[buf][idx>>6][idx&63]=rb[j];} }
  SLD(k0); SST(0);
  for(int t=0;t<nt;t++){
    __syncthreads();
    int cur=t&1;
    if(t+1<nt){ SLD(k0+(t+1)*16); }
    #pragma unroll
    for(int kk=0;kk<16;kk++){
      float4 a4=*(const float4*)&As[cur][kk][ty*4];
      ulonglong2 b2=*(const ulonglong2*)&Bs[cur][kk][tx*4];
      float av[4]={a4.x,a4.y,a4.z,a4.w};
      #pragma unroll
      for(int i=0;i<4;i++){
        ull ad=pk2(av[i],av[i]);
        acc2[i][0]=fma2(ad,b2.x,acc2[i][0]);
        acc2[i][1]=fma2(ad,b2.y,acc2[i][1]);
      }
    }
    if(t+1<nt){ SST(1-cur); }
  }
  #pragma unroll
  for(int i=0;i<4;i++){int gm=m0+ty*4+i; if(gm>=M)continue;
    float2 v0=upk2(acc2[i][0]), v1=upk2(acc2[i][1]);
    float* pr=part+((size_t)s*M+gm)*64+tx*4;
    pr[0]=v0.x; pr[1]=v0.y; pr[2]=v1.x; pr[3]=v1.y;}
  #undef SLD
  #undef SST
}

// fused gconv epilogue, 256 threads. degv!=null: deg=max(degv[j],1) (layer-0 mode)
__global__ void k_gconv_ep(const float*__restrict__ part,int nsplit,const float*__restrict__ At,
                           const float*__restrict__ degv,
                           const float*__restrict__ X,const float*__restrict__ Wrel,const float*__restrict__ brel,
                           const float*__restrict__ Wroot,float*__restrict__ Xout,float*__restrict__ xs,int n){
  int j=blockIdx.x, t=threadIdx.x; // 256
  __shared__ float agg[64], xr[64], red[256];
  float deg;
  if(degv){
    deg=fmaxf(degv[j],1.f);
  }else{
    float dc=0.f; const float* ar=At+(size_t)j*n;
    for(int i=t;i<n;i+=256) dc+=(ar[i]!=0.f)?1.f:0.f;
    red[t]=dc; __syncthreads();
    for(int st=128;st;st>>=1){if(t<st)red[t]+=red[t+st];__syncthreads();}
    deg=fmaxf(red[0],1.f);
    __syncthreads();
  }
  if(t<64){
    float sm=0.f;
    for(int q=0;q<nsplit;q++) sm+=part[((size_t)q*n+j)*64+t];
    agg[t]=sm/deg; xr[t]=X[(size_t)j*64+t];
  }
  __syncthreads();
  int c=t&63, w=t>>6;
  float o=0.f;
  for(int k=w*16;k<w*16+16;k++) o+=agg[k]*Wrel[k*64+c]+xr[k]*Wroot[k*64+c];
  red[t]=o; __syncthreads();
  if(t<64){
    float s=brel[c]+red[c]+red[64+c]+red[128+c]+red[192+c];
    s=fmaxf(s,0.f);
    Xout[(size_t)j*64+c]=s;
    atomicAdd(&xs[c],s*(1.f/(float)n));
  }
}

__global__ void k_xc_ep(const float*__restrict__ part,int nsplit,const float*__restrict__ w1,const float*__restrict__ b1v,
                        const float*__restrict__ w2,const float*__restrict__ w3,const float*__restrict__ b3v,
                        float*__restrict__ xc,float*__restrict__ a,float*__restrict__ b,float*__restrict__ c3,int n){
  int j=blockIdx.x, t=threadIdx.x; // 64
  __shared__ float r1[64],r2[64],r3[64];
  float sm=0.f;
  for(int q=0;q<nsplit;q++) sm+=part[((size_t)q*n+j)*64+t];
  xc[(size_t)j*64+t]=sm;
  r1[t]=sm*w1[t]; r2[t]=sm*w2[t]; r3[t]=sm*w3[t];
  __syncthreads();
  for(int st=32;st;st>>=1){if(t<st){r1[t]+=r1[t+st];r2[t]+=r2[t+st];r3[t]+=r3[t+st];}__syncthreads();}
  if(t==0){a[j]=r1[0]+b1v[0]; b[j]=r2[0]; c3[j]=r3[0]+b3v[0];}
}

// 128x128x16 double-buffered SGEMM, FFMA2, optional split-K.
__global__ void __launch_bounds__(256) k_gemm128(const float*__restrict__ A,const float*__restrict__ B,
                                                 float*__restrict__ C,int M,int N,int K,int TB,int ZD,int S){
  __shared__ float As[2][16][128];
  __shared__ float Bs[2][16][128];
  int tid=threadIdx.x, tx=tid&15, ty=tid>>4;
  int m0=blockIdx.y*128, n0=blockIdx.x*128;
  int KT=(K+15)/16, per=(KT+S-1)/S;
  int z=blockIdx.z;
  int ntl=min(per,KT-z*per);
  if(ntl<=0)return;
  int kb0=z*per*16;
  ull acc2[8][4]={};
  float ra[8], rb[8];
  #define LDA(k0) { \
    _Pragma("unroll") \
    for(int j=0;j<8;j++){int idx=tid*8+j; int m=idx>>4, kk=idx&15; int gm=m0+m, gk=(k0)+kk; \
      ra[j]=(gm<M&&gk<K)?A[(size_t)gm*K+gk]:0.f;} }
  #define LDB(k0) { \
    if(TB==0){ \
      _Pragma("unroll") \
      for(int j=0;j<8;j++){int idx=tid*8+j; int kk=idx>>7, nn=idx&127; int gn=n0+nn, gk=(k0)+kk; \
        rb[j]=(gn<N&&gk<K)?B[(size_t)gk*N+gn]:0.f;} \
    }else{ \
      _Pragma("unroll") \
      for(int j=0;j<8;j++){int idx=tid*8+j; int nn=idx>>4, kk=idx&15; int gn=n0+nn, gk=(k0)+kk; \
        rb[j]=(gn<N&&gk<K)?B[(size_t)gn*K+gk]:0.f;} } }
  #define STAB(buf) { \
    _Pragma("unroll") \
    for(int j=0;j<8;j++){int idx=tid*8+j; As[buf][idx&15][idx>>4]=ra[j];} \
    if(TB==0){ \
      _Pragma("unroll") \
      for(int j=0;j<8;j++){int idx=tid*8+j; Bs[buf][idx>>7][idx&127]=rb[j];} \
    }else{ \
      _Pragma("unroll") \
      for(int j=0;j<8;j++){int idx=tid*8+j; Bs[buf][idx&15][idx>>4]=rb[j];} } }
  LDA(kb0); LDB(kb0); STAB(0);
  for(int t=0;t<ntl;t++){
    __syncthreads();
    int cur=t&1;
    if(t+1<ntl){ LDA(kb0+(t+1)*16); LDB(kb0+(t+1)*16); }
    #pragma unroll
    for(int kk=0;kk<16;kk++){
      float4 a0=*(const float4*)&As[cur][kk][ty*4];
      float4 a1=*(const float4*)&As[cur][kk][64+ty*4];
      ulonglong2 b0=*(const ulonglong2*)&Bs[cur][kk][tx*4];
      ulonglong2 b1=*(const ulonglong2*)&Bs[cur][kk][64+tx*4];
      float av[8]={a0.x,a0.y,a0.z,a0.w,a1.x,a1.y,a1.z,a1.w};
      #pragma unroll
      for(int i=0;i<8;i++){
        ull ad=pk2(av[i],av[i]);
        acc2[i][0]=fma2(ad,b0.x,acc2[i][0]);
        acc2[i][1]=fma2(ad,b0.y,acc2[i][1]);
        acc2[i][2]=fma2(ad,b1.x,acc2[i][2]);
        acc2[i][3]=fma2(ad,b1.y,acc2[i][3]);
      }
    }
    if(t+1<ntl){ STAB(1-cur); }
  }
  #pragma unroll
  for(int i=0;i<8;i++){
    int gm=m0+((i<4)?(ty*4+i):(64+ty*4+i-4));
    if(gm>=M)continue;
    float* cr=C+(size_t)gm*N;
    float2 v0=upk2(acc2[i][0]), v1=upk2(acc2[i][1]), v2=upk2(acc2[i][2]), v3=upk2(acc2[i][3]);
    float cv[8]={v0.x,v0.y,v1.x,v1.y,v2.x,v2.y,v3.x,v3.y};
    #pragma unroll
    for(int j=0;j<8;j++){
      int gn=n0+((j<4)?(tx*4+j):(64+tx*4+j-4));
      if(gn>=N)continue;
      if(S==1) cr[gn]=(ZD&&gm==gn)?0.f:cv[j];
      else atomicAdd(&cr[gn],cv[j]);
    }
  }
  #undef LDA
  #undef LDB
  #undef STAB
}

__global__ void k_zdiag(float*__restrict__ A,int n){
  int i=blockIdx.x*blockDim.x+threadIdx.x; if(i<n)A[(size_t)i*n+i]=0.f;
}
__global__ void k_cntE(const int*__restrict__ ed,float*cnt){
  int e=blockIdx.x*blockDim.x+threadIdx.x; if(e<EE)atomicAdd(&cnt[ed[e]],1.f);
}
__global__ void k_scat_feat(const float*__restrict__ xw,const int*es,const int*ed,float*__restrict__ sum,int C){
  int idx=blockIdx.x*blockDim.x+threadIdx.x; if(idx>=NL*C)return;
  int e=idx/C,c=idx-e*C,s,d; ledge(e,es,ed,s,d);
  atomicAdd(&sum[d*C+c],xw[s*C+c]);
}
__global__ void k_feast_fin(const float*__restrict__ sum,const float*__restrict__ b,const float*__restrict__ cntE,
                            float*__restrict__ out,int C,int n){
  int idx=blockIdx.x*blockDim.x+threadIdx.x; if(idx>=n*C)return;
  int i=idx/C,c=idx-i*C;
  float v=sum[idx]/(cntE[i]+1.f)+b[c];
  out[idx]=(v>0.f)?v:expm1f(v);
}
__global__ void k_scat_xE(const float*__restrict__ x,const int*es,const int*ed,float*__restrict__ sum){
  int idx=blockIdx.x*blockDim.x+threadIdx.x; if(idx>=EE*64)return;
  int e=idx>>6,c=idx&63;
  atomicAdd(&sum[ed[e]*64+c],x[es[e]*64+c]);
}
__global__ void k_segmax(const float*__restrict__ x,const int*es,const int*ed,unsigned*__restrict__ enc){
  int idx=blockIdx.x*blockDim.x+threadIdx.x; if(idx>=NL*64)return;
  int e=idx>>6,c=idx&63,s,d; ledge(e,es,ed,s,d);
  atomicMax(&enc[d*64+c],fenc(x[s*64+c]));
}
__global__ void k_xq_sp(const unsigned*__restrict__ enc,const float*__restrict__ pW,const float*__restrict__ pb,
                        float*__restrict__ xq,int n){
  int j=blockIdx.x, t=threadIdx.x; // 64
  __shared__ float v[64];
  v[t]=fdec(enc[(size_t)j*64+t]);
  __syncthreads();
  float s=pb[t];
  for(int k=0;k<64;k++) s+=v[k]*pW[k*64+t];
  xq[(size_t)j*64+t]=s;
}
// fused dense-pool attention: colmax + xq GEMV + masked leaky P + row softmax; sets At diag=1
__global__ void __launch_bounds__(256) k_fusedP(float*__restrict__ At,const float*__restrict__ x,
                        const float*__restrict__ pW,const float*__restrict__ pb,
                        float*__restrict__ P,int n){
  int j0=blockIdx.x*16, tid=threadIdx.x;
  int c=tid&63, w=tid>>6;
  __shared__ float xs[16][65];
  __shared__ float mk[16][17];
  __shared__ float xq[16][65];
  __shared__ unsigned rmaxU[16];
  __shared__ float rsum[16];
  // phase A: masked colmax
  float v[4]={-3.4e38f,-3.4e38f,-3.4e38f,-3.4e38f};
  for(int i0=0;i0<n;i0+=16){
    int lim=min(16,n-i0);
    __syncthreads();
    for(int r=w;r<16;r+=4) xs[r][c]=(i0+r<n)?x[(size_t)(i0+r)*64+c]:0.f;
    {int jj=tid>>4, ii=tid&15; int gj=j0+jj, gi=i0+ii;
     mk[jj][ii]=(gj<n&&gi<n)?At[(size_t)gj*n+gi]:0.f;}
    __syncthreads();
    for(int ii=0;ii<lim;ii++){
      float xv=xs[ii][c];
      #pragma unroll
      for(int q=0;q<4;q++){ if(mk[w+4*q][ii]!=0.f || (j0+w+4*q)==(i0+ii)) v[q]=fmaxf(v[q],xv); }
    }
  }
  __syncthreads();
  #pragma unroll
  for(int q=0;q<4;q++) xq[w+4*q][c]=v[q];   // cm
  __syncthreads();
  // phase B: xq = cm@pW + pb
  float xqv[4];
  #pragma unroll
  for(int q=0;q<4;q++){
    float s=pb[c];
    for(int k=0;k<64;k++) s+=xq[w+4*q][k]*pW[k*64+c];
    xqv[q]=s;
  }
  __syncthreads();
  #pragma unroll
  for(int q=0;q<4;q++) xq[w+4*q][c]=xqv[q];
  if(tid<16){rmaxU[tid]=fenc(-3.0e38f); rsum[tid]=0.f;}
  __syncthreads();
  // phase C: masked leaky P values + row max (masked-out = -1e30)
  int jj=tid>>4, ii=tid&15;
  int gj=j0+jj;
  for(int i0=0;i0<n;i0+=16){
    __syncthreads();
    for(int r=w;r<16;r+=4) xs[r][c]=(i0+r<n)?x[(size_t)(i0+r)*64+c]:0.f;
    {int gi2=i0+ii;
     mk[jj][ii]=(gj<n&&gi2<n)?At[(size_t)gj*n+gi2]:0.f;}
    __syncthreads();
    int gi=i0+ii;
    if(gj<n&&gi<n){
      float s=0.f;
      #pragma unroll 8
      for(int k=0;k<64;k++) s+=xq[jj][k]*xs[ii][k];
      float g;
      if(mk[jj][ii]!=0.f||gj==gi){ g=(s>=0.f)?s:0.2f*s; atomicMax(&rmaxU[jj],fenc(g)); }
      else g=-1e30f;
      P[(size_t)gj*n+gi]=g;
    }
  }
  __syncthreads();
  float m=fdec(rmaxU[jj]);
  // phase D: exp + sum + normalize
  if(gj<n){
    float ls=0.f;
    float* pr=P+(size_t)gj*n;
    for(int i=ii;i<n;i+=16){ float e=expf(pr[i]-m); pr[i]=e; ls+=e; }
    atomicAdd(&rsum[jj],ls);
  }
  __syncthreads();
  if(gj<n){
    float inv=1.f/rsum[jj];
    float* pr=P+(size_t)gj*n;
    for(int i=ii;i<n;i+=16) pr[i]*=inv;
  }
  if(tid<16&&j0+tid<n) At[(size_t)(j0+tid)*n+(j0+tid)]=1.f;
}
__global__ void k_edge_s(const float*__restrict__ xq,const float*__restrict__ x,const int*es,const int*ed,
                         float*__restrict__ so,unsigned*__restrict__ um){
  int e=blockIdx.x*8+(threadIdx.x>>5), lane=threadIdx.x&31;
  if(e>=NL)return;
  int s,d; ledge(e,es,ed,s,d);
  float a=xq[d*64+lane]*x[s*64+lane]+xq[d*64+32+lane]*x[s*64+32+lane];
  #pragma unroll
  for(int o=16;o;o>>=1)a+=__shfl_xor_sync(0xffffffffu,a,o);
  if(lane==0){float v=(a>=0.f)?a:0.2f*a; so[e]=v; atomicMax(&um[d],fenc(v));}
}
__global__ void k_edge_exp(const float*__restrict__ so,const unsigned*__restrict__ um,const int*es,const int*ed,
                           float*__restrict__ eb,float*__restrict__ den){
  int e=blockIdx.x*blockDim.x+threadIdx.x; if(e>=NL)return;
  int s,d; ledge(e,es,ed,s,d);
  float v=expf(so[e]-fdec(um[d])); eb[e]=v; atomicAdd(&den[d],v);
}
__global__ void k_xc_scat(const float*__restrict__ x,const float*__restrict__ eb,const float*__restrict__ den,
                          const int*es,const int*ed,float*__restrict__ xc){
  int idx=blockIdx.x*blockDim.x+threadIdx.x; if(idx>=NL*64)return;
  int e=idx>>6,c=idx&63,s,d; ledge(e,es,ed,s,d);
  float sc=eb[e]/den[d];
  atomicAdd(&xc[d*64+c],x[s*64+c]*sc);
}
__global__ void k_abc(const float*__restrict__ xc,const float*w1,const float*b1,const float*w2,
                      const float*w3,const float*b3,float*a,float*b,float*c3,int n){
  int i=blockIdx.x*blockDim.x+threadIdx.x; if(i>=n)return;
  float s1=0,s2=0,s3=0; const float*r=xc+(size_t)i*64;
  for(int c=0;c<64;c++){float v=r[c];s1+=v*w1[c];s2+=v*w2[c];s3+=v*w3[c];}
  a[i]=s1+b1[0]; b[i]=s2; c3[i]=s3+b3[0];
}
__global__ void k_agg_edge(const float*__restrict__ a,const float*__restrict__ b,const int*es,const int*ed,
                           float*__restrict__ agg){
  int e=blockIdx.x*blockDim.x+threadIdx.x; if(e>=NL)return;
  int s,d; ledge(e,es,ed,s,d);
  atomicAdd(&agg[d],a[s]-b[d]);
}
__global__ void k_topk0(const float*__restrict__ agg,const float*__restrict__ c3,int n,int k,
                        int*__restrict__ perm,float*__restrict__ fitk){
  int i=blockIdx.x, t=threadIdx.x;
  __shared__ int red[256];
  float fi=agg[i]+c3[i]; int r=0;
  for(int j=t;j<n;j+=256){float fj=agg[j]+c3[j]; r+=(fj>fi)||(fj==fi&&j<i);}
  red[t]=r; __syncthreads();
  for(int st=128;st;st>>=1){if(t<st)red[t]+=red[t+st];__syncthreads();}
  if(t==0&&red[0]<k){perm[red[0]]=i;fitk[red[0]]=1.f/(1.f+expf(-fi));}
}
__global__ void k_topk(const float*__restrict__ fit,int n,int k,int*__restrict__ perm,float*__restrict__ fitk){
  int i=blockIdx.x, t=threadIdx.x;
  __shared__ int red[256];
  float fi=fit[i]; int r=0;
  for(int j=t;j<n;j+=256){float fj=fit[j]; r+=(fj>fi)||(fj==fi&&j<i);}
  red[t]=r; __syncthreads();
  for(int st=128;st;st>>=1){if(t<st)red[t]+=red[t+st];__syncthreads();}
  if(t==0&&red[0]<k){perm[red[0]]=i;fitk[red[0]]=fi;}
}
__global__ void k_xg(const float*__restrict__ xc,const int*__restrict__ perm,const float*__restrict__ fitk,
                     float*__restrict__ xn,const float*__restrict__ P,float*__restrict__ SpT,int n,int k){
  int idx=blockIdx.x*blockDim.x+threadIdx.x;
  if(idx<k*64){int r=idx>>6,c=idx&63; xn[idx]=xc[perm[r]*64+c]*fitk[r];}
  else{int q=idx-k*64; if(q>=k*n)return; int c=q/n,i=q-c*n; SpT[(size_t)c*n+i]=P[(size_t)perm[c]*n+i];}
}
__global__ void k_xg0(const float*__restrict__ xc,const int*__restrict__ perm,const float*__restrict__ fitk,
                      float*__restrict__ xn,int*__restrict__ inv,int k){
  int idx=blockIdx.x*blockDim.x+threadIdx.x;
  if(idx<k*64){int r=idx>>6,c=idx&63; xn[idx]=xc[perm[r]*64+c]*fitk[r];}
  else{int r=idx-k*64; if(r<k)inv[perm[r]]=r;}
}
__global__ void k_scan(const float*__restrict__ cnte,int*__restrict__ ptr,int*__restrict__ fill,int n){
  __shared__ int tmp[2048];
  int t=threadIdx.x;
  tmp[2*t]  =(2*t<n)?((int)cnte[2*t]+1):0;
  tmp[2*t+1]=(2*t+1<n)?((int)cnte[2*t+1]+1):0;
  int offset=1;
  for(int dd=1024;dd>0;dd>>=1){
    __syncthreads();
    if(t<dd){int ai=offset*(2*t+1)-1,bi=offset*(2*t+2)-1;tmp[bi]+=tmp[ai];}
    offset<<=1;
  }
  if(t==0)tmp[2047]=0;
  for(int dd=1;dd<2048;dd<<=1){
    offset>>=1;
    __syncthreads();
    if(t<dd){int ai=offset*(2*t+1)-1,bi=offset*(2*t+2)-1;int x=tmp[ai];tmp[ai]=tmp[bi];tmp[bi]+=x;}
  }
  __syncthreads();
  if(2*t<=n){ptr[2*t]=tmp[2*t];fill[2*t]=tmp[2*t];}
  if(2*t+1<=n){ptr[2*t+1]=tmp[2*t+1];fill[2*t+1]=tmp[2*t+1];}
}
__global__ void k_build(const int*es,const int*ed,const float*__restrict__ eb,const float*__restrict__ den,
                        const int*__restrict__ inv,
                        float*__restrict__ Sp,int*__restrict__ fill,int*__restrict__ csrc,float*__restrict__ csc,int k){
  int e=blockIdx.x*blockDim.x+threadIdx.x; if(e>=NL)return;
  int s,d; ledge(e,es,ed,s,d);
  float w=eb[e]/den[d];
  int c=inv[d];
  if(c>=0) atomicAdd(&Sp[(size_t)s*k+c],w);
  int pos=atomicAdd(&fill[d],1);
  csrc[pos]=s; csc[pos]=w;
}
__global__ void k_ut(const int*__restrict__ ptr,const int*__restrict__ csrc,const float*__restrict__ Sp,
                     float*__restrict__ Ut,int k){
  int i=blockIdx.x, t=threadIdx.x;
  int p0=ptr[i], p1=ptr[i+1];
  __shared__ int ss[256];
  float acc[6]={};
  for(int base=p0;base<p1;base+=256){
    int m=min(256,p1-base);
    if(t<m)ss[t]=csrc[base+t];
    __syncthreads();
    for(int q=0;q<m;q++){
      const float* sr=Sp+(size_t)ss[q]*k;
      #pragma unroll
      for(int j=0;j<6;j++){int c=t+j*256; if(c<k)acc[j]+=sr[c];}
    }
    __syncthreads();
  }
  float* ur=Ut+(size_t)i*k;
  #pragma unroll
  for(int j=0;j<6;j++){int c=t+j*256; if(c<k)ur[c]=acc[j];}
}
__global__ void k_at2(const int*__restrict__ ptr,const int*__restrict__ csrc,const float*__restrict__ csc,
                      const int*__restrict__ perm,const float*__restrict__ Ut,float*__restrict__ AT2,int k){
  int c=blockIdx.x, t=threadIdx.x;
  int node=perm[c];
  int p0=ptr[node], p1=ptr[node+1];
  __shared__ int ss[256]; __shared__ float sw[256];
  float acc[6]={};
  for(int base=p0;base<p1;base+=256){
    int m=min(256,p1-base);
    if(t<m){ss[t]=csrc[base+t];sw[t]=csc[base+t];}
    __syncthreads();
    for(int q=0;q<m;q++){
      const float* ur=Ut+(size_t)ss[q]*k;
      float w=sw[q];
      #pragma unroll
      for(int j=0;j<6;j++){int c2=t+j*256; if(c2<k)acc[j]+=w*ur[c2];}
    }
    __syncthreads();
  }
  float* ar=AT2+(size_t)c*k;
  #pragma unroll
  for(int j=0;j<6;j++){int c2=t+j*256; if(c2<k)ar[c2]=(c2==c)?0.f:acc[j];}
}
__global__ void k_aggfit(const float*__restrict__ At,const float*__restrict__ a,const float*__restrict__ b,
                         const float*__restrict__ c3,float*__restrict__ fit,int n){
  int j=blockIdx.x,t=threadIdx.x; __shared__ float r1[256],r2[256];
  const float*ar=At+(size_t)j*n; float sa=0,sc=0;
  for(int i=t;i<n;i+=256) if(ar[i]!=0.f){sa+=a[i];sc+=1.f;}
  r1[t]=sa;r2[t]=sc;__syncthreads();
  for(int st=128;st;st>>=1){if(t<st){r1[t]+=r1[t+st];r2[t]+=r2[t+st];}__syncthreads();}
  if(t==0){float v=r1[0]-r2[0]*b[j]+c3[j]; fit[j]=1.f/(1.f+expf(-v));}
}
__global__ void k_meanxs(const float*__restrict__ x,int n,float*__restrict__ dst){
  int c=blockIdx.x,t=threadIdx.x; __shared__ float red[256];
  float s=0;
  for(int i=t;i<n;i+=256)s+=x[(size_t)i*64+c];
  red[t]=s;__syncthreads();
  for(int st=128;st;st>>=1){if(t<st)red[t]+=red[t+st];__syncthreads();}
  if(t==0)dst[c]=red[0]/(float)n;
}
__global__ void k_head(const float*__restrict__ xs,const float*W1,const float*b1,const float*W2,const float*b2,
                       float*__restrict__ out){
  __shared__ float h[64],lg[10];
  int t=threadIdx.x;
  if(t<64){float s=b1[t];for(int k=0;k<640;k++)s+=xs[k]*W1[k*64+t];h[t]=fmaxf(s,0.f);}
  __syncthreads();
  if(t<10){float s=b2[t];for(int c=0;c<64;c++)s+=h[c]*W2[c*10+t];lg[t]=s;}
  __syncthreads();
  if(t==0){
    float m=lg[0];for(int j=1;j<10;j++)m=fmaxf(m,lg[j]);
    float se=0;for(int j=0;j<10;j++)se+=expf(lg[j]-m);
    float l=logf(se)+m;
    for(int j=0;j<10;j++)out[j]=lg[j]-l;
  }
}

static inline int cdiv(int a,int b){return (a+b-1)/b;}

extern "C" void kernel_launch(void* const* d_in, const int* in_sizes, int n_in,
                              void* d_out, int out_size) {
  const float* xin=(const float*)d_in[0];
  const int* es=(const int*)d_in[1];
  const int* ed=(const int*)d_in[2];
  const float* W1=(const float*)d_in[3];  const float* b1=(const float*)d_in[4];
  const float* W2=(const float*)d_in[5];  const float* b2=(const float*)d_in[6];
  const float* W3=(const float*)d_in[7];  const float* b3=(const float*)d_in[8];
  const float* Wrel=(const float*)d_in[9];const float* brel=(const float*)d_in[10];
  const float* Wroot=(const float*)d_in[11];
  const float* pW=(const float*)d_in[12]; const float* pb=(const float*)d_in[13];
  const float* leW1=(const float*)d_in[14];const float* leb1=(const float*)d_in[15];
  const float* leW2=(const float*)d_in[16];const float* leW3=(const float*)d_in[17];
  const float* leb3=(const float*)d_in[18];
  const float* linW1=(const float*)d_in[19];const float* linb1=(const float*)d_in[20];
  const float* linW2=(const float*)d_in[21];const float* linb2=(const float*)d_in[22];
  float* out=(float*)d_out;

  float* B; cudaGetSymbolAddress((void**)&B, g_buf);
  float *AT=B+O_AT, *A2=B+O_A2, *P=B+O_P, *SPT=B+O_SPT, *U=B+O_U;
  float *X=B+O_X, *XB=B+O_XB, *XQ=B+O_XQ, *XC=B+O_XC, *SUM=B+O_SUM;
  unsigned* ENC=(unsigned*)(B+O_ENC);
  float *ES=B+O_ES, *EB=B+O_EB, *MS=B+O_MS;
  float *AGG=MS+M_AGG,*DEN=MS+M_DEN,*CNTE=MS+M_CNTE;
  float *AV=MS+M_AV,*BV=MS+M_BV,*C3=MS+M_C3,*FIT=MS+M_FIT,*FITK=MS+M_FITK;
  int* PERM=(int*)(MS+M_PERM);
  float* XS=MS+M_XS;
  float* PART=U;
  int*  CPTR=(int*)P;
  int*  CFILL=(int*)(P+2000);
  int*  CSRC=(int*)(P+4000);
  float*CSC =P+30000;
  int*  INV =(int*)(P+60000);
  unsigned* UM=(unsigned*)FIT;

  int n=1500;
  cudaMemsetAsync(MS,0,15640*sizeof(float),0);
  k_cntE<<<cdiv(EE,256),256>>>(ed,CNTE);

  auto ngemm=[&](const float*A,const float*W,const float*bias,float*C,int M,int N,int K,int acc,int act){
    dim3 bd(N,256/N); k_ngemm<<<cdiv(M,bd.y),bd>>>(A,W,bias,C,M,N,K,acc,act);
  };
  auto pickS=[&](int blocks,int KT){
    long best=1L<<60; int bs=1;
    for(int s=1;s<=8;s++){
      long w=(long)((blocks*s+147)/148)*((KT+s-1)/s);
      if(w<best){best=w;bs=s;}
    }
    return bs;
  };
  auto gemm=[&](const float*A,const float*Bm,float*C,int M,int N,int K,int TB,int ZD,int wantSplit){
    int gx=cdiv(N,128), gy=cdiv(M,128);
    int S=1;
    if(wantSplit){ S=pickS(gx*gy,(K+15)/16); }
    if(S>1) cudaMemsetAsync(C,0,(size_t)M*N*sizeof(float),0);
    dim3 g(gx,gy,S);
    k_gemm128<<<g,256>>>(A,Bm,C,M,N,K,TB,(S==1)?ZD:0,S);
    if(S>1&&ZD) k_zdiag<<<cdiv(M,256),256>>>(C,M);
  };
  auto spkS=[&](int M){ int bm=cdiv(M,64); int s=148/bm; if(s<1)s=1; if(s>8)s=8; return s; };
  auto spk=[&](const float*A,const float*Xm,int M,int K,int S){
    int chunk=cdiv(cdiv(K,S),16)*16;
    dim3 g(cdiv(M,64),S); k_spk<<<g,256>>>(A,Xm,PART,M,K,chunk);
  };
  auto feast=[&](const float*src,const float*W,const float*bias,float*dst,int Cin,int Cout){
    ngemm(src,W,0,XQ,n,Cout,Cin,0,0);
    cudaMemsetAsync(SUM,0,n*Cout*sizeof(float),0);
    k_scat_feat<<<cdiv(NL*Cout,256),256>>>(XQ,es,ed,SUM,Cout);
    k_feast_fin<<<cdiv(n*Cout,256),256>>>(SUM,bias,CNTE,dst,Cout,n);
  };

  feast(xin,W1,b1,X,16,32);
  feast(X,W2,b2,XB,32,64); { float*t=X;X=XB;XB=t; }
  feast(X,W3,b3,XB,64,64); { float*t=X;X=XB;XB=t; }

  k_meanxs<<<64,256>>>(X,n,XS);
  int xsi=1, p=0;

  for(int i=0;i<9;i++){
    if(i==0){
      cudaMemsetAsync(SUM,0,n*64*sizeof(float),0);
      k_scat_xE<<<cdiv(EE*64,256),256>>>(X,es,ed,SUM);
      k_gconv_ep<<<n,256>>>(SUM,1,AT,CNTE,X,Wrel,brel,Wroot,XB,XS+xsi*64,n);
      { float*t=X;X=XB;XB=t; }
    }else{
      int S=spkS(n);
      spk(AT,X,n,n,S);
      k_gconv_ep<<<n,256>>>(PART,S,AT,(const float*)0,X,Wrel+i*4096,brel+i*64,Wroot+i*4096,XB,XS+xsi*64,n);
      { float*t=X;X=XB;XB=t; }
    }
    xsi++;

    if(i%2==0 && i<8){
      int k=(int)ceil(0.9*(double)n);
      const float *ppW=pW+p*4096,*ppb=pb+p*64,*l1=leW1+p*64,*lb1=leb1+p,*l2=leW2+p*64,*l3=leW3+p*64,*lb3=leb3+p;
      if(i==0){
        cudaMemsetAsync(XC,0,(size_t)(O_MS+M_CNTE-O_XC)*sizeof(float),0);
        cudaMemsetAsync(UM,0,n*sizeof(unsigned),0);
        k_segmax<<<cdiv(NL*64,256),256>>>(X,es,ed,ENC);
        k_xq_sp<<<n,64>>>(ENC,ppW,ppb,XB,n);
        k_edge_s<<<cdiv(NL,8),256>>>(XB,X,es,ed,ES,UM);
        k_edge_exp<<<cdiv(NL,256),256>>>(ES,UM,es,ed,EB,DEN);
        k_xc_scat<<<cdiv(NL*64,256),256>>>(X,EB,DEN,es,ed,XC);
        k_abc<<<cdiv(n,256),256>>>(XC,l1,lb1,l2,l3,lb3,AV,BV,C3,n);
        k_agg_edge<<<cdiv(NL,256),256>>>(AV,BV,es,ed,AGG);
        k_topk0<<<n,256>>>(AGG,C3,n,k,PERM,FITK);
        cudaMemsetAsync(INV,0xFF,n*sizeof(int),0);
        k_xg0<<<cdiv(k*64+k,256),256>>>(XC,PERM,FITK,XB,INV,k);
        cudaMemsetAsync(SPT,0,(size_t)n*k*sizeof(float),0);
        k_scan<<<1,1024>>>(CNTE,CPTR,CFILL,n);
        k_build<<<cdiv(NL,256),256>>>(es,ed,EB,DEN,INV,SPT,CFILL,CSRC,CSC,k);
        k_ut<<<n,256>>>(CPTR,CSRC,SPT,U,k);
        k_at2<<<k,256>>>(CPTR,CSRC,CSC,PERM,U,A2,k);
      }else{
        k_fusedP<<<cdiv(n,16),256>>>(AT,X,ppW,ppb,P,n);
        int S=spkS(n);
        spk(P,X,n,n,S);
        k_xc_ep<<<n,64>>>(PART,S,l1,lb1,l2,l3,lb3,XC,AV,BV,C3,n);
        k_aggfit<<<n,256>>>(AT,AV,BV,C3,FIT,n);
        k_topk<<<n,256>>>(FIT,n,k,PERM,FITK);
        k_xg<<<cdiv(k*64+k*n,256),256>>>(XC,PERM,FITK,XB,P,SPT,n,k);
        gemm(SPT,AT,U,k,n,n,0,0,1);
        gemm(U,SPT,A2,k,k,n,1,1,1);
      }
      { float*t=AT;AT=A2;A2=t; }
      { float*t=X;X=XB;XB=t; }
      n=k; p++;
    }
  }

  k_head<<<1,64>>>(XS,linW1,linb1,linW2,linb2,out);
  (void)in_sizes;(void)n_in;(void)out_size;
}

// round 15
// speedup vs baseline: 1.2494x; 1.2494x over previous
#include <cuda_runtime.h>
#include <math.h>

#define EE 24000
#define NTOP 1500
#define NL (EE+NTOP)
typedef unsigned long long ull;

__device__ float g_buf[11600000];

#define O_AT   0
#define O_A2   2250000
#define O_P    4500000
#define O_SPT  6750000
#define O_U    8800000
#define O_X    10850000
#define O_XB   10946000
#define O_XQ   11042000
#define O_XC   11138000
#define O_SUM  11234000
#define O_ENC  11330000
#define O_ES   11426000
#define O_EB   11452000
#define O_MS   11478000
#define M_AGG 0
#define M_DEN 1500
#define M_CNTE 3000
#define M_AV 6000
#define M_BV 7500
#define M_C3 9000
#define M_FIT 10500
#define M_FITK 12000
#define M_PERM 13500
#define M_XS 15000

__device__ __forceinline__ unsigned fenc(float f){unsigned u=__float_as_uint(f);return (u&0x80000000u)?~u:(u|0x80000000u);}
__device__ __forceinline__ float fdec(unsigned v){return (v&0x80000000u)?__uint_as_float(v&0x7FFFFFFFu):__uint_as_float(~v);}
__device__ __forceinline__ void ledge(int e,const int*es,const int*ed,int&s,int&d){ if(e<EE){s=es[e];d=ed[e];}else{s=e-EE;d=s;} }

__device__ __forceinline__ ull pk2(float x,float y){
  ull r; asm("mov.b64 %0, {%1, %2};" : "=l"(r) : "r"(__float_as_uint(x)), "r"(__float_as_uint(y))); return r;
}
__device__ __forceinline__ ull fma2(ull a,ull b,ull c){
  ull d; asm("fma.rn.f32x2 %0, %1, %2, %3;" : "=l"(d) : "l"(a), "l"(b), "l"(c)); return d;
}
__device__ __forceinline__ float2 upk2(ull v){
  unsigned lo,hi; asm("mov.b64 {%0, %1}, %2;" : "=r"(lo), "=r"(hi) : "l"(v));
  return make_float2(__uint_as_float(lo),__uint_as_float(hi));
}

// C[M,N] = act((acc?C:0) + A[M,K]@B[K,N] + bias)   (feast only)
__global__ void k_ngemm(const float*__restrict__ A,const float*__restrict__ B,const float*__restrict__ bias,
                        float*__restrict__ C,int M,int N,int K,int acc,int act){
  int col=threadIdx.x, row=blockIdx.x*blockDim.y+threadIdx.y;
  if(row>=M)return;
  float s=0.f; const float*a=A+(size_t)row*K;
  for(int k=0;k<K;k++) s+=a[k]*B[(size_t)k*N+col];
  if(bias)s+=bias[col];
  if(acc)s+=C[(size_t)row*N+col];
  if(act==1)s=fmaxf(s,0.f); else if(act==2)s=(s>0.f)?s:expm1f(s);
  C[(size_t)row*N+col]=s;
}

// split-K partial GEMM, N=64, double-buffered
__global__ void __launch_bounds__(256) k_spk(const float*__restrict__ A,const float*__restrict__ X,
                                             float*__restrict__ part,int M,int K,int chunk){
  __shared__ float As[2][16][64], Bs[2][16][64];
  int s=blockIdx.y, m0=blockIdx.x*64;
  int k0=s*chunk, k1=min(K,k0+chunk);
  int tid=threadIdx.x, tx=tid&15, ty=tid>>4;
  ull acc2[4][2]={};
  int nt=(k1-k0+15)/16;
  if(nt<=0){
    #pragma unroll
    for(int i=0;i<4;i++){int gm=m0+ty*4+i; if(gm>=M)continue;
      float* pr=part+((size_t)s*M+gm)*64+tx*4;
      pr[0]=0;pr[1]=0;pr[2]=0;pr[3]=0;}
    return;
  }
  float ra[4], rb[4];
  #define SLD(k0v) { \
    _Pragma("unroll") \
    for(int j=0;j<4;j++){int idx=tid*4+j; int m=idx>>4,kk=idx&15; int gm=m0+m,gk=(k0v)+kk; \
      ra[j]=(gm<M&&gk<k1)?A[(size_t)gm*K+gk]:0.f;} \
    _Pragma("unroll") \
    for(int j=0;j<4;j++){int idx=tid*4+j; int kk=idx>>6,nn=idx&63; int gk=(k0v)+kk; \
      rb[j]=(gk<k1)?X[(size_t)gk*64+nn]:0.f;} }
  #define SST(buf) { \
    _Pragma("unroll") \
    for(int j=0;j<4;j++){int idx=tid*4+j; As[buf][idx&15][idx>>4]=ra[j];} \
    _Pragma("unroll") \
    for(int j=0;j<4;j++){int idx=tid*4+j; Bs[buf][idx>>6][idx&63]=rb[j];} }
  SLD(k0); SST(0);
  for(int t=0;t<nt;t++){
    __syncthreads();
    int cur=t&1;
    if(t+1<nt){ SLD(k0+(t+1)*16); }
    #pragma unroll
    for(int kk=0;kk<16;kk++){
      float4 a4=*(const float4*)&As[cur][kk][ty*4];
      ulonglong2 b2=*(const ulonglong2*)&Bs[cur][kk][tx*4];
      float av[4]={a4.x,a4.y,a4.z,a4.w};
      #pragma unroll
      for(int i=0;i<4;i++){
        ull ad=pk2(av[i],av[i]);
        acc2[i][0]=fma2(ad,b2.x,acc2[i][0]);
        acc2[i][1]=fma2(ad,b2.y,acc2[i][1]);
      }
    }
    if(t+1<nt){ SST(1-cur); }
  }
  #pragma unroll
  for(int i=0;i<4;i++){int gm=m0+ty*4+i; if(gm>=M)continue;
    float2 v0=upk2(acc2[i][0]), v1=upk2(acc2[i][1]);
    float* pr=part+((size_t)s*M+gm)*64+tx*4;
    pr[0]=v0.x; pr[1]=v0.y; pr[2]=v1.x; pr[3]=v1.y;}
  #undef SLD
  #undef SST
}

// fused gconv epilogue, 256 threads. degv!=null: deg=max(degv[j],1) (layer-0 mode)
__global__ void k_gconv_ep(const float*__restrict__ part,int nsplit,const float*__restrict__ At,
                           const float*__restrict__ degv,
                           const float*__restrict__ X,const float*__restrict__ Wrel,const float*__restrict__ brel,
                           const float*__restrict__ Wroot,float*__restrict__ Xout,float*__restrict__ xs,int n){
  int j=blockIdx.x, t=threadIdx.x; // 256
  __shared__ float agg[64], xr[64], red[256];
  float deg;
  if(degv){
    deg=fmaxf(degv[j],1.f);
  }else{
    float dc=0.f; const float* ar=At+(size_t)j*n;
    for(int i=t;i<n;i+=256) dc+=(ar[i]!=0.f)?1.f:0.f;
    red[t]=dc; __syncthreads();
    for(int st=128;st;st>>=1){if(t<st)red[t]+=red[t+st];__syncthreads();}
    deg=fmaxf(red[0],1.f);
    __syncthreads();
  }
  if(t<64){
    float sm=0.f;
    for(int q=0;q<nsplit;q++) sm+=part[((size_t)q*n+j)*64+t];
    agg[t]=sm/deg; xr[t]=X[(size_t)j*64+t];
  }
  __syncthreads();
  int c=t&63, w=t>>6;
  float o=0.f;
  for(int k=w*16;k<w*16+16;k++) o+=agg[k]*Wrel[k*64+c]+xr[k]*Wroot[k*64+c];
  red[t]=o; __syncthreads();
  if(t<64){
    float s=brel[c]+red[c]+red[64+c]+red[128+c]+red[192+c];
    s=fmaxf(s,0.f);
    Xout[(size_t)j*64+c]=s;
    atomicAdd(&xs[c],s*(1.f/(float)n));
  }
}

__global__ void k_xc_ep(const float*__restrict__ part,int nsplit,const float*__restrict__ w1,const float*__restrict__ b1v,
                        const float*__restrict__ w2,const float*__restrict__ w3,const float*__restrict__ b3v,
                        float*__restrict__ xc,float*__restrict__ a,float*__restrict__ b,float*__restrict__ c3,int n){
  int j=blockIdx.x, t=threadIdx.x; // 64
  __shared__ float r1[64],r2[64],r3[64];
  float sm=0.f;
  for(int q=0;q<nsplit;q++) sm+=part[((size_t)q*n+j)*64+t];
  xc[(size_t)j*64+t]=sm;
  r1[t]=sm*w1[t]; r2[t]=sm*w2[t]; r3[t]=sm*w3[t];
  __syncthreads();
  for(int st=32;st;st>>=1){if(t<st){r1[t]+=r1[t+st];r2[t]+=r2[t+st];r3[t]+=r3[t+st];}__syncthreads();}
  if(t==0){a[j]=r1[0]+b1v[0]; b[j]=r2[0]; c3[j]=r3[0]+b3v[0];}
}

// 128x128x16 double-buffered SGEMM, FFMA2, optional split-K.
__global__ void __launch_bounds__(256) k_gemm128(const float*__restrict__ A,const float*__restrict__ B,
                                                 float*__restrict__ C,int M,int N,int K,int TB,int ZD,int S){
  __shared__ float As[2][16][128];
  __shared__ float Bs[2][16][128];
  int tid=threadIdx.x, tx=tid&15, ty=tid>>4;
  int m0=blockIdx.y*128, n0=blockIdx.x*128;
  int KT=(K+15)/16, per=(KT+S-1)/S;
  int z=blockIdx.z;
  int ntl=min(per,KT-z*per);
  if(ntl<=0)return;
  int kb0=z*per*16;
  ull acc2[8][4]={};
  float ra[8], rb[8];
  #define LDA(k0) { \
    _Pragma("unroll") \
    for(int j=0;j<8;j++){int idx=tid*8+j; int m=idx>>4, kk=idx&15; int gm=m0+m, gk=(k0)+kk; \
      ra[j]=(gm<M&&gk<K)?A[(size_t)gm*K+gk]:0.f;} }
  #define LDB(k0) { \
    if(TB==0){ \
      _Pragma("unroll") \
      for(int j=0;j<8;j++){int idx=tid*8+j; int kk=idx>>7, nn=idx&127; int gn=n0+nn, gk=(k0)+kk; \
        rb[j]=(gn<N&&gk<K)?B[(size_t)gk*N+gn]:0.f;} \
    }else{ \
      _Pragma("unroll") \
      for(int j=0;j<8;j++){int idx=tid*8+j; int nn=idx>>4, kk=idx&15; int gn=n0+nn, gk=(k0)+kk; \
        rb[j]=(gn<N&&gk<K)?B[(size_t)gn*K+gk]:0.f;} } }
  #define STAB(buf) { \
    _Pragma("unroll") \
    for(int j=0;j<8;j++){int idx=tid*8+j; As[buf][idx&15][idx>>4]=ra[j];} \
    if(TB==0){ \
      _Pragma("unroll") \
      for(int j=0;j<8;j++){int idx=tid*8+j; Bs[buf][idx>>7][idx&127]=rb[j];} \
    }else{ \
      _Pragma("unroll") \
      for(int j=0;j<8;j++){int idx=tid*8+j; Bs[buf][idx&15][idx>>4]=rb[j];} } }
  LDA(kb0); LDB(kb0); STAB(0);
  for(int t=0;t<ntl;t++){
    __syncthreads();
    int cur=t&1;
    if(t+1<ntl){ LDA(kb0+(t+1)*16); LDB(kb0+(t+1)*16); }
    #pragma unroll
    for(int kk=0;kk<16;kk++){
      float4 a0=*(const float4*)&As[cur][kk][ty*4];
      float4 a1=*(const float4*)&As[cur][kk][64+ty*4];
      ulonglong2 b0=*(const ulonglong2*)&Bs[cur][kk][tx*4];
      ulonglong2 b1=*(const ulonglong2*)&Bs[cur][kk][64+tx*4];
      float av[8]={a0.x,a0.y,a0.z,a0.w,a1.x,a1.y,a1.z,a1.w};
      #pragma unroll
      for(int i=0;i<8;i++){
        ull ad=pk2(av[i],av[i]);
        acc2[i][0]=fma2(ad,b0.x,acc2[i][0]);
        acc2[i][1]=fma2(ad,b0.y,acc2[i][1]);
        acc2[i][2]=fma2(ad,b1.x,acc2[i][2]);
        acc2[i][3]=fma2(ad,b1.y,acc2[i][3]);
      }
    }
    if(t+1<ntl){ STAB(1-cur); }
  }
  #pragma unroll
  for(int i=0;i<8;i++){
    int gm=m0+((i<4)?(ty*4+i):(64+ty*4+i-4));
    if(gm>=M)continue;
    float* cr=C+(size_t)gm*N;
    float2 v0=upk2(acc2[i][0]), v1=upk2(acc2[i][1]), v2=upk2(acc2[i][2]), v3=upk2(acc2[i][3]);
    float cv[8]={v0.x,v0.y,v1.x,v1.y,v2.x,v2.y,v3.x,v3.y};
    #pragma unroll
    for(int j=0;j<8;j++){
      int gn=n0+((j<4)?(tx*4+j):(64+tx*4+j-4));
      if(gn>=N)continue;
      if(S==1) cr[gn]=(ZD&&gm==gn)?0.f:cv[j];
      else atomicAdd(&cr[gn],cv[j]);
    }
  }
  #undef LDA
  #undef LDB
  #undef STAB
}

__global__ void k_zdiag(float*__restrict__ A,int n){
  int i=blockIdx.x*blockDim.x+threadIdx.x; if(i<n)A[(size_t)i*n+i]=0.f;
}
__global__ void k_cntE(const int*__restrict__ ed,float*cnt){
  int e=blockIdx.x*blockDim.x+threadIdx.x; if(e<EE)atomicAdd(&cnt[ed[e]],1.f);
}
__global__ void k_scat_feat(const float*__restrict__ xw,const int*es,const int*ed,float*__restrict__ sum,int C){
  int idx=blockIdx.x*blockDim.x+threadIdx.x; if(idx>=NL*C)return;
  int e=idx/C,c=idx-e*C,s,d; ledge(e,es,ed,s,d);
  atomicAdd(&sum[d*C+c],xw[s*C+c]);
}
__global__ void k_feast_fin(const float*__restrict__ sum,const float*__restrict__ b,const float*__restrict__ cntE,
                            float*__restrict__ out,int C,int n){
  int idx=blockIdx.x*blockDim.x+threadIdx.x; if(idx>=n*C)return;
  int i=idx/C,c=idx-i*C;
  float v=sum[idx]/(cntE[i]+1.f)+b[c];
  out[idx]=(v>0.f)?v:expm1f(v);
}
__global__ void k_scat_xE(const float*__restrict__ x,const int*es,const int*ed,float*__restrict__ sum){
  int idx=blockIdx.x*blockDim.x+threadIdx.x; if(idx>=EE*64)return;
  int e=idx>>6,c=idx&63;
  atomicAdd(&sum[ed[e]*64+c],x[es[e]*64+c]);
}
__global__ void k_segmax(const float*__restrict__ x,const int*es,const int*ed,unsigned*__restrict__ enc){
  int idx=blockIdx.x*blockDim.x+threadIdx.x; if(idx>=NL*64)return;
  int e=idx>>6,c=idx&63,s,d; ledge(e,es,ed,s,d);
  atomicMax(&enc[d*64+c],fenc(x[s*64+c]));
}
__global__ void k_xq_sp(const unsigned*__restrict__ enc,const float*__restrict__ pW,const float*__restrict__ pb,
                        float*__restrict__ xq,int n){
  int j=blockIdx.x, t=threadIdx.x; // 64
  __shared__ float v[64];
  v[t]=fdec(enc[(size_t)j*64+t]);
  __syncthreads();
  float s=pb[t];
  for(int k=0;k<64;k++) s+=v[k]*pW[k*64+t];
  xq[(size_t)j*64+t]=s;
}
__global__ void k_cmxq(const float*__restrict__ At,const float*__restrict__ x,const float*__restrict__ pW,
                       const float*__restrict__ pb,float*__restrict__ xq,int n){
  int j0=blockIdx.x*16, tid=threadIdx.x;
  int c=tid&63, w=tid>>6;
  __shared__ float xs[16][64];
  __shared__ float mk[16][16];
  __shared__ float cm[16][64];
  float v[4]={-3.4e38f,-3.4e38f,-3.4e38f,-3.4e38f};
  for(int i0=0;i0<n;i0+=16){
    int lim=min(16,n-i0);
    __syncthreads();
    for(int r=w;r<16;r+=4) xs[r][c]=(i0+r<n)?x[(size_t)(i0+r)*64+c]:0.f;
    {int jj=tid>>4, ii=tid&15; int gj=j0+jj, gi=i0+ii;
     mk[jj][ii]=(gj<n&&gi<n)?At[(size_t)gj*n+gi]:0.f;}
    __syncthreads();
    for(int ii=0;ii<lim;ii++){
      float xv=xs[ii][c];
      #pragma unroll
      for(int q=0;q<4;q++){ if(mk[w+4*q][ii]!=0.f || (j0+w+4*q)==(i0+ii)) v[q]=fmaxf(v[q],xv); }
    }
  }
  #pragma unroll
  for(int q=0;q<4;q++) cm[w+4*q][c]=v[q];
  __syncthreads();
  #pragma unroll
  for(int q=0;q<4;q++){
    int j=j0+w+4*q; if(j>=n)continue;
    float s=pb[c];
    for(int k=0;k<64;k++) s+=cm[w+4*q][k]*pW[k*64+c];
    xq[(size_t)j*64+c]=s;
  }
}
__global__ void k_edge_s(const float*__restrict__ xq,const float*__restrict__ x,const int*es,const int*ed,
                         float*__restrict__ so,unsigned*__restrict__ um){
  int e=blockIdx.x*8+(threadIdx.x>>5), lane=threadIdx.x&31;
  if(e>=NL)return;
  int s,d; ledge(e,es,ed,s,d);
  float a=xq[d*64+lane]*x[s*64+lane]+xq[d*64+32+lane]*x[s*64+32+lane];
  #pragma unroll
  for(int o=16;o;o>>=1)a+=__shfl_xor_sync(0xffffffffu,a,o);
  if(lane==0){float v=(a>=0.f)?a:0.2f*a; so[e]=v; atomicMax(&um[d],fenc(v));}
}
__global__ void k_edge_exp(const float*__restrict__ so,const unsigned*__restrict__ um,const int*es,const int*ed,
                           float*__restrict__ eb,float*__restrict__ den){
  int e=blockIdx.x*blockDim.x+threadIdx.x; if(e>=NL)return;
  int s,d; ledge(e,es,ed,s,d);
  float v=expf(so[e]-fdec(um[d])); eb[e]=v; atomicAdd(&den[d],v);
}
__global__ void k_xc_scat(const float*__restrict__ x,const float*__restrict__ eb,const float*__restrict__ den,
                          const int*es,const int*ed,float*__restrict__ xc){
  int idx=blockIdx.x*blockDim.x+threadIdx.x; if(idx>=NL*64)return;
  int e=idx>>6,c=idx&63,s,d; ledge(e,es,ed,s,d);
  float sc=eb[e]/den[d];
  atomicAdd(&xc[d*64+c],x[s*64+c]*sc);
}
__global__ void k_abc(const float*__restrict__ xc,const float*w1,const float*b1,const float*w2,
                      const float*w3,const float*b3,float*a,float*b,float*c3,int n){
  int i=blockIdx.x*blockDim.x+threadIdx.x; if(i>=n)return;
  float s1=0,s2=0,s3=0; const float*r=xc+(size_t)i*64;
  for(int c=0;c<64;c++){float v=r[c];s1+=v*w1[c];s2+=v*w2[c];s3+=v*w3[c];}
  a[i]=s1+b1[0]; b[i]=s2; c3[i]=s3+b3[0];
}
__global__ void k_agg_edge(const float*__restrict__ a,const float*__restrict__ b,const int*es,const int*ed,
                           float*__restrict__ agg){
  int e=blockIdx.x*blockDim.x+threadIdx.x; if(e>=NL)return;
  int s,d; ledge(e,es,ed,s,d);
  atomicAdd(&agg[d],a[s]-b[d]);
}
__global__ void k_topk0(const float*__restrict__ agg,const float*__restrict__ c3,int n,int k,
                        int*__restrict__ perm,float*__restrict__ fitk){
  int i=blockIdx.x, t=threadIdx.x;
  __shared__ int red[256];
  float fi=agg[i]+c3[i]; int r=0;
  for(int j=t;j<n;j+=256){float fj=agg[j]+c3[j]; r+=(fj>fi)||(fj==fi&&j<i);}
  red[t]=r; __syncthreads();
  for(int st=128;st;st>>=1){if(t<st)red[t]+=red[t+st];__syncthreads();}
  if(t==0&&red[0]<k){perm[red[0]]=i;fitk[red[0]]=1.f/(1.f+expf(-fi));}
}
__global__ void k_topk(const float*__restrict__ fit,int n,int k,int*__restrict__ perm,float*__restrict__ fitk){
  int i=blockIdx.x, t=threadIdx.x;
  __shared__ int red[256];
  float fi=fit[i]; int r=0;
  for(int j=t;j<n;j+=256){float fj=fit[j]; r+=(fj>fi)||(fj==fi&&j<i);}
  red[t]=r; __syncthreads();
  for(int st=128;st;st>>=1){if(t<st)red[t]+=red[t+st];__syncthreads();}
  if(t==0&&red[0]<k){perm[red[0]]=i;fitk[red[0]]=fi;}
}
__global__ void k_xg(const float*__restrict__ xc,const int*__restrict__ perm,const float*__restrict__ fitk,
                     float*__restrict__ xn,const float*__restrict__ P,float*__restrict__ SpT,int n,int k){
  int idx=blockIdx.x*blockDim.x+threadIdx.x;
  if(idx<k*64){int r=idx>>6,c=idx&63; xn[idx]=xc[perm[r]*64+c]*fitk[r];}
  else{int q=idx-k*64; if(q>=k*n)return; int c=q/n,i=q-c*n; SpT[(size_t)c*n+i]=P[(size_t)perm[c]*n+i];}
}
__global__ void k_xg0(const float*__restrict__ xc,const int*__restrict__ perm,const float*__restrict__ fitk,
                      float*__restrict__ xn,int*__restrict__ inv,int k){
  int idx=blockIdx.x*blockDim.x+threadIdx.x;
  if(idx<k*64){int r=idx>>6,c=idx&63; xn[idx]=xc[perm[r]*64+c]*fitk[r];}
  else{int r=idx-k*64; if(r<k)inv[perm[r]]=r;}
}
// exclusive scan of (cntE[d]+1) into ptr AND fill; also inits inv[0..n)=-1
__global__ void k_scan(const float*__restrict__ cnte,int*__restrict__ ptr,int*__restrict__ fill,
                       int*__restrict__ inv,int n){
  __shared__ int tmp[2048];
  int t=threadIdx.x;
  for(int i=t;i<n;i+=1024) inv[i]=-1;
  tmp[2*t]  =(2*t<n)?((int)cnte[2*t]+1):0;
  tmp[2*t+1]=(2*t+1<n)?((int)cnte[2*t+1]+1):0;
  int offset=1;
  for(int dd=1024;dd>0;dd>>=1){
    __syncthreads();
    if(t<dd){int ai=offset*(2*t+1)-1,bi=offset*(2*t+2)-1;tmp[bi]+=tmp[ai];}
    offset<<=1;
  }
  if(t==0)tmp[2047]=0;
  for(int dd=1;dd<2048;dd<<=1){
    offset>>=1;
    __syncthreads();
    if(t<dd){int ai=offset*(2*t+1)-1,bi=offset*(2*t+2)-1;int x=tmp[ai];tmp[ai]=tmp[bi];tmp[bi]+=x;}
  }
  __syncthreads();
  if(2*t<=n){ptr[2*t]=tmp[2*t];fill[2*t]=tmp[2*t];}
  if(2*t+1<=n){ptr[2*t+1]=tmp[2*t+1];fill[2*t+1]=tmp[2*t+1];}
}
__global__ void k_build(const int*es,const int*ed,const float*__restrict__ eb,const float*__restrict__ den,
                        const int*__restrict__ inv,
                        float*__restrict__ Sp,int*__restrict__ fill,int*__restrict__ csrc,float*__restrict__ csc,int k){
  int e=blockIdx.x*blockDim.x+threadIdx.x; if(e>=NL)return;
  int s,d; ledge(e,es,ed,s,d);
  float w=eb[e]/den[d];
  int c=inv[d];
  if(c>=0) atomicAdd(&Sp[(size_t)s*k+c],w);
  int pos=atomicAdd(&fill[d],1);
  csrc[pos]=s; csc[pos]=w;
}
__global__ void k_ut(const int*__restrict__ ptr,const int*__restrict__ csrc,const float*__restrict__ Sp,
                     float*__restrict__ Ut,int k){
  int i=blockIdx.x, t=threadIdx.x;
  int p0=ptr[i], p1=ptr[i+1];
  __shared__ int ss[256];
  float acc[6]={};
  for(int base=p0;base<p1;base+=256){
    int m=min(256,p1-base);
    if(t<m)ss[t]=csrc[base+t];
    __syncthreads();
    for(int q=0;q<m;q++){
      const float* sr=Sp+(size_t)ss[q]*k;
      #pragma unroll
      for(int j=0;j<6;j++){int c=t+j*256; if(c<k)acc[j]+=sr[c];}
    }
    __syncthreads();
  }
  float* ur=Ut+(size_t)i*k;
  #pragma unroll
  for(int j=0;j<6;j++){int c=t+j*256; if(c<k)ur[c]=acc[j];}
}
__global__ void k_at2(const int*__restrict__ ptr,const int*__restrict__ csrc,const float*__restrict__ csc,
                      const int*__restrict__ perm,const float*__restrict__ Ut,float*__restrict__ AT2,int k){
  int c=blockIdx.x, t=threadIdx.x;
  int node=perm[c];
  int p0=ptr[node], p1=ptr[node+1];
  __shared__ int ss[256]; __shared__ float sw[256];
  float acc[6]={};
  for(int base=p0;base<p1;base+=256){
    int m=min(256,p1-base);
    if(t<m){ss[t]=csrc[base+t];sw[t]=csc[base+t];}
    __syncthreads();
    for(int q=0;q<m;q++){
      const float* ur=Ut+(size_t)ss[q]*k;
      float w=sw[q];
      #pragma unroll
      for(int j=0;j<6;j++){int c2=t+j*256; if(c2<k)acc[j]+=w*ur[c2];}
    }
    __syncthreads();
  }
  float* ar=AT2+(size_t)c*k;
  #pragma unroll
  for(int j=0;j<6;j++){int c2=t+j*256; if(c2<k)ar[c2]=(c2==c)?0.f:acc[j];}
}
__global__ void k_rowsm(float*__restrict__ P,float*__restrict__ At,int n){
  int j=blockIdx.x,t=threadIdx.x; __shared__ float red[256];
  float*ar=At+(size_t)j*n; float*pr=P+(size_t)j*n;
  if(t==0) ar[j]=1.f;
  __syncthreads();
  float m=-3.4e38f;
  for(int i=t;i<n;i+=256) if(ar[i]!=0.f||i==j){float g=pr[i];g=(g>=0.f)?g:0.2f*g;m=fmaxf(m,g);}
  red[t]=m;__syncthreads();
  for(int st=128;st;st>>=1){if(t<st)red[t]=fmaxf(red[t],red[t+st]);__syncthreads();}
  m=red[0];__syncthreads();
  float s=0;
  for(int i=t;i<n;i+=256){
    float e=0.f;
    if(ar[i]!=0.f||i==j){float g=pr[i];g=(g>=0.f)?g:0.2f*g;e=expf(g-m);}
    pr[i]=e;s+=e;
  }
  red[t]=s;__syncthreads();
  for(int st=128;st;st>>=1){if(t<st)red[t]+=red[t+st];__syncthreads();}
  float inv=1.f/red[0];
  for(int i=t;i<n;i+=256)pr[i]*=inv;
}
__global__ void k_aggfit(const float*__restrict__ At,const float*__restrict__ a,const float*__restrict__ b,
                         const float*__restrict__ c3,float*__restrict__ fit,int n){
  int j=blockIdx.x,t=threadIdx.x; __shared__ float r1[256],r2[256];
  const float*ar=At+(size_t)j*n; float sa=0,sc=0;
  for(int i=t;i<n;i+=256) if(ar[i]!=0.f){sa+=a[i];sc+=1.f;}
  r1[t]=sa;r2[t]=sc;__syncthreads();
  for(int st=128;st;st>>=1){if(t<st){r1[t]+=r1[t+st];r2[t]+=r2[t+st];}__syncthreads();}
  if(t==0){float v=r1[0]-r2[0]*b[j]+c3[j]; fit[j]=1.f/(1.f+expf(-v));}
}
__global__ void k_meanxs(const float*__restrict__ x,int n,float*__restrict__ dst){
  int c=blockIdx.x,t=threadIdx.x; __shared__ float red[256];
  float s=0;
  for(int i=t;i<n;i+=256)s+=x[(size_t)i*64+c];
  red[t]=s;__syncthreads();
  for(int st=128;st;st>>=1){if(t<st)red[t]+=red[t+st];__syncthreads();}
  if(t==0)dst[c]=red[0]/(float)n;
}
__global__ void k_head(const float*__restrict__ xs,const float*W1,const float*b1,const float*W2,const float*b2,
                       float*__restrict__ out){
  __shared__ float h[64],lg[10];
  int t=threadIdx.x;
  if(t<64){float s=b1[t];for(int k=0;k<640;k++)s+=xs[k]*W1[k*64+t];h[t]=fmaxf(s,0.f);}
  __syncthreads();
  if(t<10){float s=b2[t];for(int c=0;c<64;c++)s+=h[c]*W2[c*10+t];lg[t]=s;}
  __syncthreads();
  if(t==0){
    float m=lg[0];for(int j=1;j<10;j++)m=fmaxf(m,lg[j]);
    float se=0;for(int j=0;j<10;j++)se+=expf(lg[j]-m);
    float l=logf(se)+m;
    for(int j=0;j<10;j++)out[j]=lg[j]-l;
  }
}

static inline int cdiv(int a,int b){return (a+b-1)/b;}

extern "C" void kernel_launch(void* const* d_in, const int* in_sizes, int n_in,
                              void* d_out, int out_size) {
  const float* xin=(const float*)d_in[0];
  const int* es=(const int*)d_in[1];
  const int* ed=(const int*)d_in[2];
  const float* W1=(const float*)d_in[3];  const float* b1=(const float*)d_in[4];
  const float* W2=(const float*)d_in[5];  const float* b2=(const float*)d_in[6];
  const float* W3=(const float*)d_in[7];  const float* b3=(const float*)d_in[8];
  const float* Wrel=(const float*)d_in[9];const float* brel=(const float*)d_in[10];
  const float* Wroot=(const float*)d_in[11];
  const float* pW=(const float*)d_in[12]; const float* pb=(const float*)d_in[13];
  const float* leW1=(const float*)d_in[14];const float* leb1=(const float*)d_in[15];
  const float* leW2=(const float*)d_in[16];const float* leW3=(const float*)d_in[17];
  const float* leb3=(const float*)d_in[18];
  const float* linW1=(const float*)d_in[19];const float* linb1=(const float*)d_in[20];
  const float* linW2=(const float*)d_in[21];const float* linb2=(const float*)d_in[22];
  float* out=(float*)d_out;

  float* B; cudaGetSymbolAddress((void**)&B, g_buf);
  float *AT=B+O_AT, *A2=B+O_A2, *P=B+O_P, *SPT=B+O_SPT, *U=B+O_U;
  float *X=B+O_X, *XB=B+O_XB, *XQ=B+O_XQ, *XC=B+O_XC, *SUM=B+O_SUM;
  unsigned* ENC=(unsigned*)(B+O_ENC);
  float *ES=B+O_ES, *EB=B+O_EB, *MS=B+O_MS;
  float *AGG=MS+M_AGG,*DEN=MS+M_DEN,*CNTE=MS+M_CNTE;
  float *AV=MS+M_AV,*BV=MS+M_BV,*C3=MS+M_C3,*FIT=MS+M_FIT,*FITK=MS+M_FITK;
  int* PERM=(int*)(MS+M_PERM);
  float* XS=MS+M_XS;
  float* PART=U;
  int*  CPTR=(int*)P;
  int*  CFILL=(int*)(P+2000);
  int*  CSRC=(int*)(P+4000);
  float*CSC =P+30000;
  int*  INV =(int*)(P+60000);
  unsigned* UM=(unsigned*)FIT;  // pool-0 max scratch (FIT zeroed at init, unwritten before pool 0)

  int n=1500;
  cudaMemsetAsync(MS,0,15640*sizeof(float),0);
  k_cntE<<<cdiv(EE,256),256>>>(ed,CNTE);

  auto ngemm=[&](const float*A,const float*W,const float*bias,float*C,int M,int N,int K,int acc,int act){
    dim3 bd(N,256/N); k_ngemm<<<cdiv(M,bd.y),bd>>>(A,W,bias,C,M,N,K,acc,act);
  };
  auto pickS=[&](int blocks,int KT){
    long best=1L<<60; int bs=1;
    for(int s=1;s<=8;s++){
      long w=(long)((blocks*s+147)/148)*((KT+s-1)/s);
      if(w<best){best=w;bs=s;}
    }
    return bs;
  };
  auto gemm=[&](const float*A,const float*Bm,float*C,int M,int N,int K,int TB,int ZD,int wantSplit){
    int gx=cdiv(N,128), gy=cdiv(M,128);
    int S=1;
    if(wantSplit){ S=pickS(gx*gy,(K+15)/16); }
    if(S>1) cudaMemsetAsync(C,0,(size_t)M*N*sizeof(float),0);
    dim3 g(gx,gy,S);
    k_gemm128<<<g,256>>>(A,Bm,C,M,N,K,TB,(S==1)?ZD:0,S);
    if(S>1&&ZD) k_zdiag<<<cdiv(M,256),256>>>(C,M);
  };
  auto spkS=[&](int M){ int bm=cdiv(M,64); int s=148/bm; if(s<1)s=1; if(s>8)s=8; return s; };
  auto spk=[&](const float*A,const float*Xm,int M,int K,int S){
    int chunk=cdiv(cdiv(K,S),16)*16;
    dim3 g(cdiv(M,64),S); k_spk<<<g,256>>>(A,Xm,PART,M,K,chunk);
  };
  auto feast=[&](const float*src,const float*W,const float*bias,float*dst,int Cin,int Cout){
    ngemm(src,W,0,XQ,n,Cout,Cin,0,0);
    cudaMemsetAsync(SUM,0,n*Cout*sizeof(float),0);
    k_scat_feat<<<cdiv(NL*Cout,256),256>>>(XQ,es,ed,SUM,Cout);
    k_feast_fin<<<cdiv(n*Cout,256),256>>>(SUM,bias,CNTE,dst,Cout,n);
  };

  feast(xin,W1,b1,X,16,32);
  feast(X,W2,b2,XB,32,64); { float*t=X;X=XB;XB=t; }
  feast(X,W3,b3,XB,64,64); { float*t=X;X=XB;XB=t; }

  k_meanxs<<<64,256>>>(X,n,XS);
  int xsi=1, p=0;

  for(int i=0;i<9;i++){
    if(i==0){
      cudaMemsetAsync(SUM,0,n*64*sizeof(float),0);
      k_scat_xE<<<cdiv(EE*64,256),256>>>(X,es,ed,SUM);
      k_gconv_ep<<<n,256>>>(SUM,1,AT,CNTE,X,Wrel,brel,Wroot,XB,XS+xsi*64,n);
      { float*t=X;X=XB;XB=t; }
    }else{
      int S=spkS(n);
      spk(AT,X,n,n,S);
      k_gconv_ep<<<n,256>>>(PART,S,AT,(const float*)0,X,Wrel+i*4096,brel+i*64,Wroot+i*4096,XB,XS+xsi*64,n);
      { float*t=X;X=XB;XB=t; }
    }
    xsi++;

    if(i%2==0 && i<8){
      int k=(int)ceil(0.9*(double)n);
      const float *ppW=pW+p*4096,*ppb=pb+p*64,*l1=leW1+p*64,*lb1=leb1+p,*l2=leW2+p*64,*l3=leW3+p*64,*lb3=leb3+p;
      if(i==0){
        // big memset zeroes XC,SUM,ENC,ES,EB,AGG,DEN; UM(=FIT) still zero from init memset
        cudaMemsetAsync(XC,0,(size_t)(O_MS+M_CNTE-O_XC)*sizeof(float),0);
        k_segmax<<<cdiv(NL*64,256),256>>>(X,es,ed,ENC);
        k_xq_sp<<<n,64>>>(ENC,ppW,ppb,XB,n);
        k_edge_s<<<cdiv(NL,8),256>>>(XB,X,es,ed,ES,UM);
        k_edge_exp<<<cdiv(NL,256),256>>>(ES,UM,es,ed,EB,DEN);
        k_xc_scat<<<cdiv(NL*64,256),256>>>(X,EB,DEN,es,ed,XC);
        k_abc<<<cdiv(n,256),256>>>(XC,l1,lb1,l2,l3,lb3,AV,BV,C3,n);
        k_agg_edge<<<cdiv(NL,256),256>>>(AV,BV,es,ed,AGG);
        k_topk0<<<n,256>>>(AGG,C3,n,k,PERM,FITK);
        k_scan<<<1,1024>>>(CNTE,CPTR,CFILL,INV,n);   // also inits INV=-1
        k_xg0<<<cdiv(k*64+k,256),256>>>(XC,PERM,FITK,XB,INV,k);
        cudaMemsetAsync(SPT,0,(size_t)n*k*sizeof(float),0);
        k_build<<<cdiv(NL,256),256>>>(es,ed,EB,DEN,INV,SPT,CFILL,CSRC,CSC,k);
        k_ut<<<n,256>>>(CPTR,CSRC,SPT,U,k);
        k_at2<<<k,256>>>(CPTR,CSRC,CSC,PERM,U,A2,k);
      }else{
        k_cmxq<<<cdiv(n,16),256>>>(AT,X,ppW,ppb,XB,n);
        gemm(XB,X,P,n,n,64,1,0,0);
        k_rowsm<<<n,256>>>(P,AT,n);
        int S=spkS(n);
        spk(P,X,n,n,S);
        k_xc_ep<<<n,64>>>(PART,S,l1,lb1,l2,l3,lb3,XC,AV,BV,C3,n);
        k_aggfit<<<n,256>>>(AT,AV,BV,C3,FIT,n);
        k_topk<<<n,256>>>(FIT,n,k,PERM,FITK);
        k_xg<<<cdiv(k*64+k*n,256),256>>>(XC,PERM,FITK,XB,P,SPT,n,k);
        gemm(SPT,AT,U,k,n,n,0,0,1);
        gemm(U,SPT,A2,k,k,n,1,1,1);
      }
      { float*t=AT;AT=A2;A2=t; }
      { float*t=X;X=XB;XB=t; }
      n=k; p++;
    }
  }

  k_head<<<1,64>>>(XS,linW1,linb1,linW2,linb2,out);
  (void)in_sizes;(void)n_in;(void)out_size;
}